// round 3
// baseline (speedup 1.0000x reference)
#include <cuda_runtime.h>
#include <math.h>

#define SS 1024
#define CC 4096
#define KK 4
#define NB 128          // blocks
#define RPB 8           // s-rows per block  (NB*RPB == SS)

// ---------------- scratch (no allocations allowed) ----------------
__device__ float g_sums[8 * SS];   // raw dots  sum_j exp(logPi[c_k][j]) * recip[s][j]
__device__ float g_logcnt[SS];
__device__ float g_logE[SS];
__device__ unsigned int g_counter = 0;

__device__ __forceinline__ float softplusf(float x) {
    if (x > 20.0f)  return x;
    if (x < -20.0f) return expf(x);
    return log1pf(expf(x));
}

__device__ __forceinline__ float laef(float a, float b) {
    float mx = fmaxf(a, b);
    float mn = fminf(a, b);
    return mx + log1pf(expf(mn - mx));
}

__global__ void __launch_bounds__(256) k_fused(
    const float* __restrict__ log_delta,
    const float* __restrict__ log_tau,
    const float* __restrict__ log_lambda,
    const float* __restrict__ E,
    const float* __restrict__ logPi,
    const int*   __restrict__ sC1,
    const int*   __restrict__ sC2,
    const float* __restrict__ recip,
    const int*   __restrict__ splits_c1,
    const int*   __restrict__ splits_c2,
    const float* __restrict__ log_q,
    const void*  __restrict__ is_leaf,
    const int*   __restrict__ rootp,
    float*       __restrict__ out)
{
    const int tid  = threadIdx.x;          // 0..255  (one float4 slot of the 1024-wide row)
    const int b    = blockIdx.x;
    const int w    = tid >> 5, lane = tid & 31;

    // ---- per-block scalar constants (redundant per block; all loads L2-hot broadcasts) ----
    const int root = rootp[0];
    const float delta = softplusf(log_delta[0]);
    const float tau   = softplusf(log_tau[0]);
    const float lam   = softplusf(log_lambda[0]);
    const float rs = 1.0f + delta + tau + lam;
    const float pS = 1.0f / rs, pD = delta / rs, pT = tau / rs, pL = lam / rs;

    int c[8];
    #pragma unroll
    for (int k = 0; k < KK; k++) {
        c[k]     = splits_c1[root * KK + k];
        c[4 + k] = splits_c2[root * KK + k];
    }

    // ---- per-thread weights: w[k] = exp(logPi[c_k][j]) for this thread's float4 slot ----
    float4 wv[8];
    #pragma unroll
    for (int k = 0; k < 8; k++) {
        float4 v = ((const float4*)(logPi + (size_t)c[k] * SS))[tid];
        wv[k].x = expf(v.x); wv[k].y = expf(v.y); wv[k].z = expf(v.z); wv[k].w = expf(v.w);
    }
    const float4 ev = ((const float4*)E)[tid];

    __shared__ float sm[8][10];

    // ---- main loop: 8 recip rows per block ----
    for (int r = 0; r < RPB; r++) {
        const int s = b * RPB + r;
        const float4 rv = ((const float4*)(recip + (size_t)s * SS))[tid];

        float acc[10];
        acc[0] = rv.x + rv.y + rv.z + rv.w;
        acc[1] = rv.x * ev.x + rv.y * ev.y + rv.z * ev.z + rv.w * ev.w;
        #pragma unroll
        for (int k = 0; k < 8; k++)
            acc[2 + k] = rv.x * wv[k].x + rv.y * wv[k].y + rv.z * wv[k].z + rv.w * wv[k].w;

        #pragma unroll
        for (int q = 0; q < 10; q++)
            #pragma unroll
            for (int o = 16; o > 0; o >>= 1)
                acc[q] += __shfl_xor_sync(0xffffffffu, acc[q], o);

        if (lane == 0)
            #pragma unroll
            for (int q = 0; q < 10; q++) sm[w][q] = acc[q];
        __syncthreads();

        if (tid == 0) {
            float tot[10];
            #pragma unroll
            for (int q = 0; q < 10; q++) {
                float t = 0.0f;
                #pragma unroll
                for (int w2 = 0; w2 < 8; w2++) t += sm[w2][q];
                tot[q] = t;
            }
            float cnt = fmaxf(tot[0], 1.0f);
            g_logcnt[s] = logf(cnt);
            float Ebar = tot[1] / cnt;
            float Es = E[s];
            float Enew = pL + pD * Es * Es + pT * Es * Ebar + pS * E[sC1[s]] * E[sC2[s]];
            g_logE[s] = logf(Enew);
            #pragma unroll
            for (int k = 0; k < 8; k++) g_sums[k * SS + s] = tot[2 + k];
        }
        __syncthreads();
    }

    // ---- grid-wide completion: last block runs the epilogue ----
    __shared__ unsigned int s_islast;
    __threadfence();
    if (tid == 0) {
        unsigned int prev = atomicAdd(&g_counter, 1u);
        s_islast = (prev == (unsigned int)(NB - 1)) ? 1u : 0u;
    }
    __syncthreads();
    if (!s_islast) return;
    __threadfence();   // acquire: make all blocks' g_* writes visible

    // ---- epilogue: root-row combined + global LSE (256 threads x 4 s-values) ----
    const unsigned char* lb = (const unsigned char*)is_leaf;
    const unsigned int*  lw = (const unsigned int*)is_leaf;
    const bool leaf = (lb[root] != 0) || (lw[root] == 0x3F800000u);
    const float lpS = logf(pS), lpD = logf(pD), lpT = logf(pT);
    const float* rootRow = logPi + (size_t)root * SS;

    float m_loc = -INFINITY, s_loc = 0.0f;

    #pragma unroll
    for (int u = 0; u < 4; u++) {
        const int s = tid + u * 256;
        float m1, s1;
        if (leaf) {
            m1 = rootRow[s]; s1 = 1.0f;
        } else {
            int i1 = sC1[s], i2 = sC2[s];
            float lct = g_logcnt[s];

            float speck[KK], dupk[KK], trk[KK];
            float specm = -INFINITY, dupm = -INFINITY, trm = -INFINITY;
            #pragma unroll
            for (int k = 0; k < KK; k++) {
                const float* rA = logPi + (size_t)c[k] * SS;
                const float* rB = logPi + (size_t)c[4 + k] * SS;
                float a  = rA[s],  bb = rB[s];
                float af = rA[i1], ag = rA[i2];
                float bf = rB[i1], bg = rB[i2];
                float lq = log_q[root * KK + k];

                speck[k] = lq + laef(af + bg, ag + bf);
                dupk[k]  = lq + a + bb;
                float tbA = logf(fmaxf(g_sums[k * SS + s],       1e-30f)) - lct;
                float tbB = logf(fmaxf(g_sums[(4 + k) * SS + s], 1e-30f)) - lct;
                trk[k] = lq + laef(a + tbB, bb + tbA);

                specm = fmaxf(specm, speck[k]);
                dupm  = fmaxf(dupm,  dupk[k]);
                trm   = fmaxf(trm,   trk[k]);
            }
            float se = 0.0f, de = 0.0f, te = 0.0f;
            #pragma unroll
            for (int k = 0; k < KK; k++) {
                se += expf(speck[k] - specm);
                de += expf(dupk[k]  - dupm);
                te += expf(trk[k]   - trm);
            }
            float spec  = lpS + specm + logf(se);
            float dup   = lpD + dupm  + logf(de);
            float trans = lpT + trm   + logf(te);
            float sl    = lpS + laef(rootRow[i1] + g_logE[i2],
                                     rootRow[i2] + g_logE[i1]);

            m1 = fmaxf(fmaxf(spec, dup), fmaxf(trans, sl));
            s1 = expf(spec - m1) + expf(dup - m1) + expf(trans - m1) + expf(sl - m1);
        }
        // online merge into (m_loc, s_loc)
        float M = fmaxf(m_loc, m1);
        s_loc = s_loc * expf(m_loc - M) + s1 * expf(m1 - M);
        m_loc = M;
    }

    // block LSE reduction over 256 threads
    __shared__ float shm[256];
    __shared__ float shs[256];
    shm[tid] = m_loc; shs[tid] = s_loc;
    __syncthreads();
    for (int stride = 128; stride > 0; stride >>= 1) {
        if (tid < stride) {
            float m1 = shm[tid], s1 = shs[tid];
            float m2 = shm[tid + stride], s2 = shs[tid + stride];
            float M = fmaxf(m1, m2);
            shm[tid] = M;
            shs[tid] = s1 * expf(m1 - M) + s2 * expf(m2 - M);
        }
        __syncthreads();
    }
    if (tid == 0) {
        out[0] = shm[0] + logf(shs[0]);
        atomicExch(&g_counter, 0u);   // reset for next graph replay
    }
}

// ---------------- launch ----------------
extern "C" void kernel_launch(void* const* d_in, const int* in_sizes, int n_in,
                              void* d_out, int out_size)
{
    const float* log_delta  = (const float*)d_in[0];
    const float* log_tau    = (const float*)d_in[1];
    const float* log_lambda = (const float*)d_in[2];
    const float* E          = (const float*)d_in[3];
    const float* log_Pi     = (const float*)d_in[4];
    const int*   s_C1       = (const int*)  d_in[5];
    const int*   s_C2       = (const int*)  d_in[6];
    const float* recip      = (const float*)d_in[7];
    const int*   splits_c1  = (const int*)  d_in[8];
    const int*   splits_c2  = (const int*)  d_in[9];
    const float* log_q      = (const float*)d_in[10];
    const void*  is_leaf    = (const void*) d_in[11];
    const int*   root_id    = (const int*)  d_in[12];
    float* out = (float*)d_out;

    k_fused<<<NB, 256>>>(log_delta, log_tau, log_lambda, E, log_Pi,
                         s_C1, s_C2, recip, splits_c1, splits_c2,
                         log_q, is_leaf, root_id, out);
}

// round 4
// speedup vs baseline: 1.2297x; 1.2297x over previous
#include <cuda_runtime.h>
#include <math.h>

#define SS 1024
#define CC 4096
#define KK 4
#define NB 128          // blocks in kernel A (NB * 8 warps == SS rows)

// ---------------- scratch (no allocations allowed) ----------------
__device__ float g_sums[8 * SS];   // raw dots  sum_j exp(logPi[c_k][j]) * recip[s][j]
__device__ float g_logcnt[SS];
__device__ float g_logE[SS];

__device__ __forceinline__ float softplusf(float x) {
    if (x > 20.0f)  return x;
    if (x < -20.0f) return expf(x);
    return log1pf(expf(x));
}

__device__ __forceinline__ float laef(float a, float b) {
    float mx = fmaxf(a, b);
    float mn = fminf(a, b);
    return mx + log1pf(expf(mn - mx));
}

// ============ kernel A: streaming pass over Recipients_mat, warp-per-row ============
__global__ void __launch_bounds__(256) kA(
    const float* __restrict__ log_delta,
    const float* __restrict__ log_tau,
    const float* __restrict__ log_lambda,
    const float* __restrict__ E,
    const float* __restrict__ logPi,
    const int*   __restrict__ sC1,
    const int*   __restrict__ sC2,
    const float* __restrict__ recip,
    const int*   __restrict__ splits_c1,
    const int*   __restrict__ splits_c2,
    const int*   __restrict__ rootp)
{
    __shared__ float sw[8 * SS];   // exp(logPi[c_k][j])  (32 KB)
    __shared__ float sE[SS];       // E (4 KB)

    const int tid  = threadIdx.x;
    const int b    = blockIdx.x;
    const int warp = tid >> 5, lane = tid & 31;

    // scalar constants (uniform, L2-hot broadcasts)
    const int root = rootp[0];
    const float delta = softplusf(log_delta[0]);
    const float tau   = softplusf(log_tau[0]);
    const float lam   = softplusf(log_lambda[0]);
    const float rs = 1.0f + delta + tau + lam;
    const float pS = 1.0f / rs, pD = delta / rs, pT = tau / rs, pL = lam / rs;

    // ---- stage weights + E in shared ----
    #pragma unroll
    for (int k = 0; k < 8; k++) {
        int c = (k < 4) ? splits_c1[root * KK + k] : splits_c2[root * KK + (k - 4)];
        float4 v = ((const float4*)(logPi + (size_t)c * SS))[tid];
        float4 w;
        w.x = expf(v.x); w.y = expf(v.y); w.z = expf(v.z); w.w = expf(v.w);
        ((float4*)(sw + k * SS))[tid] = w;
    }
    ((float4*)sE)[tid] = ((const float4*)E)[tid];
    __syncthreads();

    // ---- warp-per-row: s = b*8 + warp ----
    const int s = b * 8 + warp;
    const float4* rrow = (const float4*)(recip + (size_t)s * SS);
    const float4* sE4  = (const float4*)sE;

    float acc[10];
    #pragma unroll
    for (int q = 0; q < 10; q++) acc[q] = 0.0f;

    #pragma unroll
    for (int it = 0; it < 8; it++) {
        const int j4 = lane + it * 32;          // float4 index within the row
        const float4 rv = rrow[j4];
        const float4 ev = sE4[j4];
        acc[0] += rv.x + rv.y + rv.z + rv.w;
        acc[1] += rv.x * ev.x + rv.y * ev.y + rv.z * ev.z + rv.w * ev.w;
        #pragma unroll
        for (int k = 0; k < 8; k++) {
            const float4 wv = ((const float4*)(sw + k * SS))[j4];
            acc[2 + k] += rv.x * wv.x + rv.y * wv.y + rv.z * wv.z + rv.w * wv.w;
        }
    }

    #pragma unroll
    for (int q = 0; q < 10; q++)
        #pragma unroll
        for (int o = 16; o > 0; o >>= 1)
            acc[q] += __shfl_xor_sync(0xffffffffu, acc[q], o);

    if (lane == 0) {
        float cnt = fmaxf(acc[0], 1.0f);
        g_logcnt[s] = logf(cnt);
        float Ebar = acc[1] / cnt;
        float Es = sE[s & (SS - 1)];   // s < SS always; sE holds full E
        float Enew = pL + pD * Es * Es + pT * Es * Ebar + pS * E[sC1[s]] * E[sC2[s]];
        g_logE[s] = logf(Enew);
        #pragma unroll
        for (int k = 0; k < 8; k++) g_sums[k * SS + s] = acc[2 + k];
    }
}

// ============ kernel B: root-row epilogue + global LSE ============
__global__ void __launch_bounds__(1024) kB(
    const float* __restrict__ log_delta,
    const float* __restrict__ log_tau,
    const float* __restrict__ log_lambda,
    const float* __restrict__ logPi,
    const float* __restrict__ log_q,
    const int*   __restrict__ sC1,
    const int*   __restrict__ sC2,
    const int*   __restrict__ splits_c1,
    const int*   __restrict__ splits_c2,
    const void*  __restrict__ is_leaf,
    const int*   __restrict__ rootp,
    float*       __restrict__ out)
{
    const int s = threadIdx.x;       // one thread per s
    const int root = rootp[0];

    const float delta = softplusf(log_delta[0]);
    const float tau   = softplusf(log_tau[0]);
    const float lam   = softplusf(log_lambda[0]);
    const float rs = 1.0f + delta + tau + lam;
    const float lpS = logf(1.0f / rs), lpD = logf(delta / rs), lpT = logf(tau / rs);

    // leaf flag, robust to serialization dtype (bool/uint8, int32, or float32)
    const unsigned char* lb = (const unsigned char*)is_leaf;
    const unsigned int*  lw = (const unsigned int*)is_leaf;
    const bool leaf = (lb[root] != 0) || (lw[root] == 0x3F800000u);

    int c[8];
    #pragma unroll
    for (int k = 0; k < KK; k++) {
        c[k]     = splits_c1[root * KK + k];
        c[4 + k] = splits_c2[root * KK + k];
    }
    const float* rootRow = logPi + (size_t)root * SS;

    float m_loc, s_loc;
    if (leaf) {
        m_loc = rootRow[s];
        s_loc = 1.0f;
    } else {
        int i1 = sC1[s], i2 = sC2[s];
        float lct = g_logcnt[s];

        float speck[KK], dupk[KK], trk[KK];
        float specm = -INFINITY, dupm = -INFINITY, trm = -INFINITY;
        #pragma unroll
        for (int k = 0; k < KK; k++) {
            const float* rA = logPi + (size_t)c[k] * SS;
            const float* rB = logPi + (size_t)c[4 + k] * SS;
            float a  = rA[s],  bb = rB[s];
            float af = rA[i1], ag = rA[i2];
            float bf = rB[i1], bg = rB[i2];
            float lq = log_q[root * KK + k];

            speck[k] = lq + laef(af + bg, ag + bf);
            dupk[k]  = lq + a + bb;
            // logTbar = log(max(raw_sum,1e-30)) - log(cnt)   (max-shift m == 0, exact identity)
            float tbA = logf(fmaxf(g_sums[k * SS + s],       1e-30f)) - lct;
            float tbB = logf(fmaxf(g_sums[(4 + k) * SS + s], 1e-30f)) - lct;
            trk[k] = lq + laef(a + tbB, bb + tbA);

            specm = fmaxf(specm, speck[k]);
            dupm  = fmaxf(dupm,  dupk[k]);
            trm   = fmaxf(trm,   trk[k]);
        }
        float se = 0.0f, de = 0.0f, te = 0.0f;
        #pragma unroll
        for (int k = 0; k < KK; k++) {
            se += expf(speck[k] - specm);
            de += expf(dupk[k]  - dupm);
            te += expf(trk[k]   - trm);
        }
        float spec  = lpS + specm + logf(se);
        float dup   = lpD + dupm  + logf(de);
        float trans = lpT + trm   + logf(te);
        float sl    = lpS + laef(rootRow[i1] + g_logE[i2],
                                 rootRow[i2] + g_logE[i1]);

        float mx = fmaxf(fmaxf(spec, dup), fmaxf(trans, sl));
        m_loc = mx;
        s_loc = expf(spec - mx) + expf(dup - mx) + expf(trans - mx) + expf(sl - mx);
    }

    // block-wide online LSE reduction over 1024 (m, sum) pairs
    __shared__ float shm[SS];
    __shared__ float shs[SS];
    shm[s] = m_loc; shs[s] = s_loc;
    __syncthreads();
    for (int stride = 512; stride > 0; stride >>= 1) {
        if (s < stride) {
            float m1 = shm[s], s1 = shs[s];
            float m2 = shm[s + stride], s2 = shs[s + stride];
            float M = fmaxf(m1, m2);
            shm[s] = M;
            shs[s] = s1 * expf(m1 - M) + s2 * expf(m2 - M);
        }
        __syncthreads();
    }
    if (s == 0) out[0] = shm[0] + logf(shs[0]);
}

// ---------------- launch ----------------
extern "C" void kernel_launch(void* const* d_in, const int* in_sizes, int n_in,
                              void* d_out, int out_size)
{
    const float* log_delta  = (const float*)d_in[0];
    const float* log_tau    = (const float*)d_in[1];
    const float* log_lambda = (const float*)d_in[2];
    const float* E          = (const float*)d_in[3];
    const float* log_Pi     = (const float*)d_in[4];
    const int*   s_C1       = (const int*)  d_in[5];
    const int*   s_C2       = (const int*)  d_in[6];
    const float* recip      = (const float*)d_in[7];
    const int*   splits_c1  = (const int*)  d_in[8];
    const int*   splits_c2  = (const int*)  d_in[9];
    const float* log_q      = (const float*)d_in[10];
    const void*  is_leaf    = (const void*) d_in[11];
    const int*   root_id    = (const int*)  d_in[12];
    float* out = (float*)d_out;

    kA<<<NB, 256>>>(log_delta, log_tau, log_lambda, E, log_Pi,
                    s_C1, s_C2, recip, splits_c1, splits_c2, root_id);
    kB<<<1, 1024>>>(log_delta, log_tau, log_lambda, log_Pi, log_q,
                    s_C1, s_C2, splits_c1, splits_c2, is_leaf, root_id, out);
}

// round 5
// speedup vs baseline: 1.5690x; 1.2759x over previous
#include <cuda_runtime.h>
#include <math.h>

#define SS 1024
#define CC 4096
#define KK 4
#define NB 128          // blocks in kernel A (NB * 8 warps == SS rows)
#define NB2 32          // blocks in kernel B (NB2 * 32 lanes == SS)

// ---------------- scratch (no allocations allowed) ----------------
__device__ float g_sums[8 * SS];   // raw dots  sum_j exp(logPi[c_k][j]) * recip[s][j]
__device__ float g_logcnt[SS];
__device__ float g_logE[SS];
__device__ float g_pm[NB2];        // per-block partial LSE max
__device__ float g_ps[NB2];        // per-block partial LSE sum
__device__ unsigned int g_counter = 0;

__device__ __forceinline__ float softplusf(float x) {
    if (x > 20.0f)  return x;
    if (x < -20.0f) return expf(x);
    return log1pf(expf(x));
}

__device__ __forceinline__ float laef(float a, float b) {
    float mx = fmaxf(a, b);
    float mn = fminf(a, b);
    return mx + log1pf(expf(mn - mx));
}

// ============ kernel A: streaming pass over Recipients_mat, warp-per-row ============
__global__ void __launch_bounds__(256) kA(
    const float* __restrict__ log_delta,
    const float* __restrict__ log_tau,
    const float* __restrict__ log_lambda,
    const float* __restrict__ E,
    const float* __restrict__ logPi,
    const int*   __restrict__ sC1,
    const int*   __restrict__ sC2,
    const float* __restrict__ recip,
    const int*   __restrict__ splits_c1,
    const int*   __restrict__ splits_c2,
    const int*   __restrict__ rootp)
{
    __shared__ float sw[8 * SS];   // exp(logPi[c_k][j])  (32 KB)
    __shared__ float sE[SS];       // E (4 KB)

    const int tid  = threadIdx.x;
    const int b    = blockIdx.x;
    const int warp = tid >> 5, lane = tid & 31;

    // scalar constants (uniform, L2-hot broadcasts)
    const int root = rootp[0];
    const float delta = softplusf(log_delta[0]);
    const float tau   = softplusf(log_tau[0]);
    const float lam   = softplusf(log_lambda[0]);
    const float rs = 1.0f + delta + tau + lam;
    const float pS = 1.0f / rs, pD = delta / rs, pT = tau / rs, pL = lam / rs;

    // ---- stage weights + E in shared ----
    #pragma unroll
    for (int k = 0; k < 8; k++) {
        int c = (k < 4) ? splits_c1[root * KK + k] : splits_c2[root * KK + (k - 4)];
        float4 v = ((const float4*)(logPi + (size_t)c * SS))[tid];
        float4 w;
        w.x = expf(v.x); w.y = expf(v.y); w.z = expf(v.z); w.w = expf(v.w);
        ((float4*)(sw + k * SS))[tid] = w;
    }
    ((float4*)sE)[tid] = ((const float4*)E)[tid];
    __syncthreads();

    // ---- warp-per-row: s = b*8 + warp ----
    const int s = b * 8 + warp;
    const float4* rrow = (const float4*)(recip + (size_t)s * SS);
    const float4* sE4  = (const float4*)sE;

    float acc[10];
    #pragma unroll
    for (int q = 0; q < 10; q++) acc[q] = 0.0f;

    #pragma unroll
    for (int it = 0; it < 8; it++) {
        const int j4 = lane + it * 32;          // float4 index within the row
        const float4 rv = rrow[j4];
        const float4 ev = sE4[j4];
        acc[0] += rv.x + rv.y + rv.z + rv.w;
        acc[1] += rv.x * ev.x + rv.y * ev.y + rv.z * ev.z + rv.w * ev.w;
        #pragma unroll
        for (int k = 0; k < 8; k++) {
            const float4 wv = ((const float4*)(sw + k * SS))[j4];
            acc[2 + k] += rv.x * wv.x + rv.y * wv.y + rv.z * wv.z + rv.w * wv.w;
        }
    }

    #pragma unroll
    for (int q = 0; q < 10; q++)
        #pragma unroll
        for (int o = 16; o > 0; o >>= 1)
            acc[q] += __shfl_xor_sync(0xffffffffu, acc[q], o);

    if (lane == 0) {
        float cnt = fmaxf(acc[0], 1.0f);
        g_logcnt[s] = logf(cnt);
        float Ebar = acc[1] / cnt;
        float Es = sE[s];
        float Enew = pL + pD * Es * Es + pT * Es * Ebar + pS * E[sC1[s]] * E[sC2[s]];
        g_logE[s] = logf(Enew);
        #pragma unroll
        for (int k = 0; k < 8; k++) g_sums[k * SS + s] = acc[2 + k];
    }
}

// ============ kernel B: root-row epilogue + global LSE, 32 blocks x 1 warp ============
__global__ void __launch_bounds__(32) kB(
    const float* __restrict__ log_delta,
    const float* __restrict__ log_tau,
    const float* __restrict__ log_lambda,
    const float* __restrict__ logPi,
    const float* __restrict__ log_q,
    const int*   __restrict__ sC1,
    const int*   __restrict__ sC2,
    const int*   __restrict__ splits_c1,
    const int*   __restrict__ splits_c2,
    const void*  __restrict__ is_leaf,
    const int*   __restrict__ rootp,
    float*       __restrict__ out)
{
    const int lane = threadIdx.x;            // 0..31
    const int b    = blockIdx.x;             // 0..31
    const int root = rootp[0];

    const float delta = softplusf(log_delta[0]);
    const float tau   = softplusf(log_tau[0]);
    const float lam   = softplusf(log_lambda[0]);
    const float rs = 1.0f + delta + tau + lam;
    const float lpS = logf(1.0f / rs), lpD = logf(delta / rs), lpT = logf(tau / rs);

    // leaf flag, robust to serialization dtype (bool/uint8, int32, or float32)
    const unsigned char* lb = (const unsigned char*)is_leaf;
    const unsigned int*  lw = (const unsigned int*)is_leaf;
    const bool leaf = (lb[root] != 0) || (lw[root] == 0x3F800000u);

    int c[8];
    #pragma unroll
    for (int k = 0; k < KK; k++) {
        c[k]     = splits_c1[root * KK + k];
        c[4 + k] = splits_c2[root * KK + k];
    }
    const float* rootRow = logPi + (size_t)root * SS;

    // 32 s-values per block, one per lane
    const int s = b * 32 + lane;

    float m_loc, s_loc;
    if (leaf) {
        m_loc = rootRow[s];
        s_loc = 1.0f;
    } else {
        int i1 = sC1[s], i2 = sC2[s];
        float lct = g_logcnt[s];

        float speck[KK], dupk[KK], trk[KK];
        float specm = -INFINITY, dupm = -INFINITY, trm = -INFINITY;
        #pragma unroll
        for (int k = 0; k < KK; k++) {
            const float* rA = logPi + (size_t)c[k] * SS;
            const float* rB = logPi + (size_t)c[4 + k] * SS;
            float a  = rA[s],  bb = rB[s];
            float af = rA[i1], ag = rA[i2];
            float bf = rB[i1], bg = rB[i2];
            float lq = log_q[root * KK + k];

            speck[k] = lq + laef(af + bg, ag + bf);
            dupk[k]  = lq + a + bb;
            // logTbar = log(max(raw_sum,1e-30)) - log(cnt)   (max-shift m == 0, exact identity)
            float tbA = logf(fmaxf(g_sums[k * SS + s],       1e-30f)) - lct;
            float tbB = logf(fmaxf(g_sums[(4 + k) * SS + s], 1e-30f)) - lct;
            trk[k] = lq + laef(a + tbB, bb + tbA);

            specm = fmaxf(specm, speck[k]);
            dupm  = fmaxf(dupm,  dupk[k]);
            trm   = fmaxf(trm,   trk[k]);
        }
        float se = 0.0f, de = 0.0f, te = 0.0f;
        #pragma unroll
        for (int k = 0; k < KK; k++) {
            se += expf(speck[k] - specm);
            de += expf(dupk[k]  - dupm);
            te += expf(trk[k]   - trm);
        }
        float spec  = lpS + specm + logf(se);
        float dup   = lpD + dupm  + logf(de);
        float trans = lpT + trm   + logf(te);
        float sl    = lpS + laef(rootRow[i1] + g_logE[i2],
                                 rootRow[i2] + g_logE[i1]);

        float mx = fmaxf(fmaxf(spec, dup), fmaxf(trans, sl));
        m_loc = mx;
        s_loc = expf(spec - mx) + expf(dup - mx) + expf(trans - mx) + expf(sl - mx);
    }

    // warp LSE reduction
    #pragma unroll
    for (int o = 16; o > 0; o >>= 1) {
        float m2 = __shfl_xor_sync(0xffffffffu, m_loc, o);
        float s2 = __shfl_xor_sync(0xffffffffu, s_loc, o);
        float M = fmaxf(m_loc, m2);
        s_loc = s_loc * expf(m_loc - M) + s2 * expf(m2 - M);
        m_loc = M;
    }

    __shared__ unsigned int s_islast;
    if (lane == 0) {
        g_pm[b] = m_loc;
        g_ps[b] = s_loc;
        __threadfence();
        unsigned int prev = atomicAdd(&g_counter, 1u);
        s_islast = (prev == (unsigned int)(NB2 - 1)) ? 1u : 0u;
    }
    __syncwarp();
    unsigned int islast = __shfl_sync(0xffffffffu, s_islast, 0);
    if (!islast) return;
    __threadfence();   // acquire: all partials visible

    // final reduction over 32 partials (one per lane)
    float m1 = g_pm[lane];
    float s1 = g_ps[lane];
    #pragma unroll
    for (int o = 16; o > 0; o >>= 1) {
        float m2 = __shfl_xor_sync(0xffffffffu, m1, o);
        float s2 = __shfl_xor_sync(0xffffffffu, s1, o);
        float M = fmaxf(m1, m2);
        s1 = s1 * expf(m1 - M) + s2 * expf(m2 - M);
        m1 = M;
    }
    if (lane == 0) {
        out[0] = m1 + logf(s1);
        atomicExch(&g_counter, 0u);   // reset for next graph replay
    }
}

// ---------------- launch ----------------
extern "C" void kernel_launch(void* const* d_in, const int* in_sizes, int n_in,
                              void* d_out, int out_size)
{
    const float* log_delta  = (const float*)d_in[0];
    const float* log_tau    = (const float*)d_in[1];
    const float* log_lambda = (const float*)d_in[2];
    const float* E          = (const float*)d_in[3];
    const float* log_Pi     = (const float*)d_in[4];
    const int*   s_C1       = (const int*)  d_in[5];
    const int*   s_C2       = (const int*)  d_in[6];
    const float* recip      = (const float*)d_in[7];
    const int*   splits_c1  = (const int*)  d_in[8];
    const int*   splits_c2  = (const int*)  d_in[9];
    const float* log_q      = (const float*)d_in[10];
    const void*  is_leaf    = (const void*) d_in[11];
    const int*   root_id    = (const int*)  d_in[12];
    float* out = (float*)d_out;

    kA<<<NB, 256>>>(log_delta, log_tau, log_lambda, E, log_Pi,
                    s_C1, s_C2, recip, splits_c1, splits_c2, root_id);
    kB<<<NB2, 32>>>(log_delta, log_tau, log_lambda, log_Pi, log_q,
                    s_C1, s_C2, splits_c1, splits_c2, is_leaf, root_id, out);
}

// round 6
// speedup vs baseline: 1.5724x; 1.0022x over previous
#include <cuda_runtime.h>
#include <math.h>

#define SS 1024
#define CC 4096
#define KK 4
#define NB 128          // blocks in kernel A (NB * 8 warps == SS rows)
#define NB2 32          // blocks in kernel B (NB2 * 32 lanes == SS)

// ---------------- scratch (no allocations allowed) ----------------
__device__ float g_sums[8 * SS];   // linear dots  sum_j exp(logPi[c_k][j]) * recip[s][j]
__device__ float g_P[9 * SS];      // exp(logPi) rows: 0..3 = c1 splits, 4..7 = c2 splits, 8 = root
__device__ float g_invcnt[SS];     // 1 / cnt[s]
__device__ float g_En[SS];         // E_new[s]  (linear)
__device__ float g_ps[NB2];        // per-block partial sums of lin[s]
__device__ unsigned int g_counter = 0;

__device__ __forceinline__ float softplusf(float x) {
    if (x > 20.0f)  return x;
    if (x < -20.0f) return expf(x);
    return log1pf(expf(x));
}

// ============ kernel A: streaming pass over Recipients_mat, warp-per-row ============
__global__ void __launch_bounds__(256) kA(
    const float* __restrict__ log_delta,
    const float* __restrict__ log_tau,
    const float* __restrict__ log_lambda,
    const float* __restrict__ E,
    const float* __restrict__ logPi,
    const int*   __restrict__ sC1,
    const int*   __restrict__ sC2,
    const float* __restrict__ recip,
    const int*   __restrict__ splits_c1,
    const int*   __restrict__ splits_c2,
    const int*   __restrict__ rootp)
{
    __shared__ float sw[8 * SS];   // exp(logPi[c_k][j])  (32 KB)
    __shared__ float sE[SS];       // E (4 KB)

    const int tid  = threadIdx.x;
    const int b    = blockIdx.x;
    const int warp = tid >> 5, lane = tid & 31;

    // scalar constants (uniform, L2-hot broadcasts)
    const int root = rootp[0];
    const float delta = softplusf(log_delta[0]);
    const float tau   = softplusf(log_tau[0]);
    const float lam   = softplusf(log_lambda[0]);
    const float rs = 1.0f + delta + tau + lam;
    const float pS = 1.0f / rs, pD = delta / rs, pT = tau / rs, pL = lam / rs;

    // ---- stage weights + E in shared ----
    #pragma unroll
    for (int k = 0; k < 8; k++) {
        int c = (k < 4) ? splits_c1[root * KK + k] : splits_c2[root * KK + (k - 4)];
        float4 v = ((const float4*)(logPi + (size_t)c * SS))[tid];
        float4 w;
        w.x = expf(v.x); w.y = expf(v.y); w.z = expf(v.z); w.w = expf(v.w);
        ((float4*)(sw + k * SS))[tid] = w;
    }
    ((float4*)sE)[tid] = ((const float4*)E)[tid];

    // blocks 0..8 additionally publish the exp'd rows to global scratch for kB
    if (b < 8) {
        // note: sw write above by this same thread, no sync needed for own float4
        float4 w = ((const float4*)(logPi + 0))[0]; (void)w; // placeholder no-op avoided below
    }
    __syncthreads();

    if (b < 8) {
        ((float4*)(g_P + b * SS))[tid] = ((const float4*)(sw + b * SS))[tid];
    } else if (b == 8) {
        float4 v = ((const float4*)(logPi + (size_t)root * SS))[tid];
        float4 w;
        w.x = expf(v.x); w.y = expf(v.y); w.z = expf(v.z); w.w = expf(v.w);
        ((float4*)(g_P + 8 * SS))[tid] = w;
    }

    // ---- warp-per-row: s = b*8 + warp ----
    const int s = b * 8 + warp;
    const float4* rrow = (const float4*)(recip + (size_t)s * SS);
    const float4* sE4  = (const float4*)sE;

    float acc[10];
    #pragma unroll
    for (int q = 0; q < 10; q++) acc[q] = 0.0f;

    #pragma unroll
    for (int it = 0; it < 8; it++) {
        const int j4 = lane + it * 32;          // float4 index within the row
        const float4 rv = rrow[j4];
        const float4 ev = sE4[j4];
        acc[0] += rv.x + rv.y + rv.z + rv.w;
        acc[1] += rv.x * ev.x + rv.y * ev.y + rv.z * ev.z + rv.w * ev.w;
        #pragma unroll
        for (int k = 0; k < 8; k++) {
            const float4 wv = ((const float4*)(sw + k * SS))[j4];
            acc[2 + k] += rv.x * wv.x + rv.y * wv.y + rv.z * wv.z + rv.w * wv.w;
        }
    }

    #pragma unroll
    for (int q = 0; q < 10; q++)
        #pragma unroll
        for (int o = 16; o > 0; o >>= 1)
            acc[q] += __shfl_xor_sync(0xffffffffu, acc[q], o);

    if (lane == 0) {
        float cnt = fmaxf(acc[0], 1.0f);
        float inv = 1.0f / cnt;
        g_invcnt[s] = inv;
        float Ebar = acc[1] * inv;
        float Es = sE[s];
        float Enew = pL + pD * Es * Es + pT * Es * Ebar + pS * E[sC1[s]] * E[sC2[s]];
        g_En[s] = Enew;
        #pragma unroll
        for (int k = 0; k < 8; k++) g_sums[k * SS + s] = acc[2 + k];
    }
}

// ============ kernel B: linear-domain epilogue + global sum, 32 blocks x 1 warp ============
__global__ void __launch_bounds__(32) kB(
    const float* __restrict__ log_delta,
    const float* __restrict__ log_tau,
    const float* __restrict__ log_lambda,
    const float* __restrict__ logPi,
    const float* __restrict__ log_q,
    const int*   __restrict__ sC1,
    const int*   __restrict__ sC2,
    const void*  __restrict__ is_leaf,
    const int*   __restrict__ rootp,
    float*       __restrict__ out)
{
    const int lane = threadIdx.x;            // 0..31
    const int b    = blockIdx.x;             // 0..31
    const int root = rootp[0];

    const float delta = softplusf(log_delta[0]);
    const float tau   = softplusf(log_tau[0]);
    const float lam   = softplusf(log_lambda[0]);
    const float rs = 1.0f + delta + tau + lam;
    const float pS = 1.0f / rs, pD = delta / rs, pT = tau / rs;

    // leaf flag, robust to serialization dtype (bool/uint8, int32, or float32)
    const unsigned char* lb = (const unsigned char*)is_leaf;
    const unsigned int*  lw = (const unsigned int*)is_leaf;
    const bool leaf = (lb[root] != 0) || (lw[root] == 0x3F800000u);

    // q_k = exp(log_q[root][k])  (uniform)
    float qs[KK];
    #pragma unroll
    for (int k = 0; k < KK; k++) qs[k] = expf(log_q[root * KK + k]);

    const int s = b * 32 + lane;

    float lin;
    if (leaf) {
        lin = g_P[8 * SS + s];
    } else {
        const int i1 = sC1[s], i2 = sC2[s];
        const float inv = g_invcnt[s];

        float spec_acc = 0.0f, dup_acc = 0.0f, trans_acc = 0.0f;
        #pragma unroll
        for (int k = 0; k < KK; k++) {
            const float* PA = g_P + k * SS;        // c1[k] row (linear)
            const float* PB = g_P + (4 + k) * SS;  // c2[k] row (linear)
            float A  = PA[s],  B  = PB[s];
            float Af = PA[i1], Ag = PA[i2];
            float Bf = PB[i1], Bg = PB[i2];
            float q  = qs[k];
            spec_acc  += q * (Af * Bg + Ag * Bf);
            dup_acc   += q * (A * B);
            trans_acc += q * (A * g_sums[(4 + k) * SS + s] + B * g_sums[k * SS + s]);
        }
        float sl = g_P[8 * SS + i1] * g_En[i2] + g_P[8 * SS + i2] * g_En[i1];
        lin = pS * spec_acc + pD * dup_acc + pT * inv * trans_acc + pS * sl;
    }

    // warp sum
    #pragma unroll
    for (int o = 16; o > 0; o >>= 1)
        lin += __shfl_xor_sync(0xffffffffu, lin, o);

    __shared__ unsigned int s_islast;
    if (lane == 0) {
        g_ps[b] = lin;
        __threadfence();
        unsigned int prev = atomicAdd(&g_counter, 1u);
        s_islast = (prev == (unsigned int)(NB2 - 1)) ? 1u : 0u;
    }
    __syncwarp();
    unsigned int islast = __shfl_sync(0xffffffffu, s_islast, 0);
    if (!islast) return;
    __threadfence();   // acquire: all partials visible

    // final: sum 32 partials (one per lane), one log
    float v = g_ps[lane];
    #pragma unroll
    for (int o = 16; o > 0; o >>= 1)
        v += __shfl_xor_sync(0xffffffffu, v, o);
    if (lane == 0) {
        out[0] = logf(v);
        atomicExch(&g_counter, 0u);   // reset for next graph replay
    }
}

// ---------------- launch ----------------
extern "C" void kernel_launch(void* const* d_in, const int* in_sizes, int n_in,
                              void* d_out, int out_size)
{
    const float* log_delta  = (const float*)d_in[0];
    const float* log_tau    = (const float*)d_in[1];
    const float* log_lambda = (const float*)d_in[2];
    const float* E          = (const float*)d_in[3];
    const float* log_Pi     = (const float*)d_in[4];
    const int*   s_C1       = (const int*)  d_in[5];
    const int*   s_C2       = (const int*)  d_in[6];
    const float* recip      = (const float*)d_in[7];
    const int*   splits_c1  = (const int*)  d_in[8];
    const int*   splits_c2  = (const int*)  d_in[9];
    const float* log_q      = (const float*)d_in[10];
    const void*  is_leaf    = (const void*) d_in[11];
    const int*   root_id    = (const int*)  d_in[12];
    float* out = (float*)d_out;

    kA<<<NB, 256>>>(log_delta, log_tau, log_lambda, E, log_Pi,
                    s_C1, s_C2, recip, splits_c1, splits_c2, root_id);
    kB<<<NB2, 32>>>(log_delta, log_tau, log_lambda, log_Pi, log_q,
                    s_C1, s_C2, is_leaf, root_id, out);
}

// round 7
// speedup vs baseline: 1.6360x; 1.0404x over previous
#include <cuda_runtime.h>
#include <math.h>

#define SS 1024
#define CC 4096
#define KK 4
#define NB 128          // blocks (NB * 8 warps == SS rows); NB <= SM count -> co-resident

// ---------------- scratch (no allocations allowed) ----------------
__device__ float g_sums[8 * SS];   // linear dots  sum_j exp(logPi[c_k][j]) * recip[s][j]
__device__ float g_P[9 * SS];      // exp(logPi) rows: 0..3 = c1 splits, 4..7 = c2 splits, 8 = root
__device__ float g_invcnt[SS];     // 1 / cnt[s]
__device__ float g_En[SS];         // E_new[s]  (linear)
__device__ float g_ps[NB];         // per-block partial sums of lin[s]
__device__ unsigned int g_bar1 = 0, g_bar2 = 0;   // monotonic ticket counters (never reset)

__device__ __forceinline__ float softplusf(float x) {
    if (x > 20.0f)  return x;
    if (x < -20.0f) return expf(x);
    return log1pf(expf(x));
}

// Grid barrier: monotonic counter, replay-safe (no reset), wrap-safe compare.
// All NB blocks are co-resident (NB <= 148 SMs), so spin cannot deadlock.
__device__ __forceinline__ void grid_barrier(unsigned int* bar) {
    __threadfence();                       // release: my writes visible before arrive
    __syncthreads();
    if (threadIdx.x == 0) {
        unsigned int t = atomicAdd(bar, 1u);
        unsigned int target = (t / NB + 1u) * NB;   // end of this launch's round
        while ((int)(*(volatile unsigned int*)bar - target) < 0) { }
    }
    __syncthreads();
    __threadfence();                       // acquire: others' writes visible after
}

__global__ void __launch_bounds__(256) k_fused(
    const float* __restrict__ log_delta,
    const float* __restrict__ log_tau,
    const float* __restrict__ log_lambda,
    const float* __restrict__ E,
    const float* __restrict__ logPi,
    const int*   __restrict__ sC1,
    const int*   __restrict__ sC2,
    const float* __restrict__ recip,
    const int*   __restrict__ splits_c1,
    const int*   __restrict__ splits_c2,
    const float* __restrict__ log_q,
    const void*  __restrict__ is_leaf,
    const int*   __restrict__ rootp,
    float*       __restrict__ out)
{
    __shared__ float sw[8 * SS];   // exp(logPi[c_k][j])  (32 KB)
    __shared__ float sE[SS];       // E (4 KB)
    __shared__ float s_part[8];    // per-warp epilogue partials

    const int tid  = threadIdx.x;
    const int b    = blockIdx.x;
    const int warp = tid >> 5, lane = tid & 31;

    // ---- scalar constants (uniform, L2-hot broadcasts) ----
    const int root = rootp[0];
    const float delta = softplusf(log_delta[0]);
    const float tau   = softplusf(log_tau[0]);
    const float lam   = softplusf(log_lambda[0]);
    const float rs = 1.0f + delta + tau + lam;
    const float pS = 1.0f / rs, pD = delta / rs, pT = tau / rs, pL = lam / rs;

    // ---- stage weights + E in shared ----
    #pragma unroll
    for (int k = 0; k < 8; k++) {
        int c = (k < 4) ? splits_c1[root * KK + k] : splits_c2[root * KK + (k - 4)];
        float4 v = ((const float4*)(logPi + (size_t)c * SS))[tid];
        float4 w;
        w.x = expf(v.x); w.y = expf(v.y); w.z = expf(v.z); w.w = expf(v.w);
        ((float4*)(sw + k * SS))[tid] = w;
    }
    ((float4*)sE)[tid] = ((const float4*)E)[tid];

    // blocks 0..7 publish exp'd split rows; block 8 publishes exp'd root row
    if (b < 8) {
        // own thread wrote this float4 above; no cross-thread dependency
        float4 w = ((const float4*)(sw + b * SS))[tid];
        ((float4*)(g_P + b * SS))[tid] = w;
    } else if (b == 8) {
        float4 v = ((const float4*)(logPi + (size_t)root * SS))[tid];
        float4 w;
        w.x = expf(v.x); w.y = expf(v.y); w.z = expf(v.z); w.w = expf(v.w);
        ((float4*)(g_P + 8 * SS))[tid] = w;
    }
    __syncthreads();

    // ---- row phase: warp-per-row, s = b*8 + warp ----
    {
        const int s = b * 8 + warp;
        const float4* rrow = (const float4*)(recip + (size_t)s * SS);
        const float4* sE4  = (const float4*)sE;

        float acc[10];
        #pragma unroll
        for (int q = 0; q < 10; q++) acc[q] = 0.0f;

        #pragma unroll
        for (int it = 0; it < 8; it++) {
            const int j4 = lane + it * 32;
            const float4 rv = rrow[j4];
            const float4 ev = sE4[j4];
            acc[0] += rv.x + rv.y + rv.z + rv.w;
            acc[1] += rv.x * ev.x + rv.y * ev.y + rv.z * ev.z + rv.w * ev.w;
            #pragma unroll
            for (int k = 0; k < 8; k++) {
                const float4 wv = ((const float4*)(sw + k * SS))[j4];
                acc[2 + k] += rv.x * wv.x + rv.y * wv.y + rv.z * wv.z + rv.w * wv.w;
            }
        }

        #pragma unroll
        for (int q = 0; q < 10; q++)
            #pragma unroll
            for (int o = 16; o > 0; o >>= 1)
                acc[q] += __shfl_xor_sync(0xffffffffu, acc[q], o);

        if (lane == 0) {
            float cnt = fmaxf(acc[0], 1.0f);
            float inv = 1.0f / cnt;
            g_invcnt[s] = inv;
            float Ebar = acc[1] * inv;
            float Es = sE[s];
            float Enew = pL + pD * Es * Es + pT * Es * Ebar + pS * E[sC1[s]] * E[sC2[s]];
            g_En[s] = Enew;
            #pragma unroll
            for (int k = 0; k < 8; k++) g_sums[k * SS + s] = acc[2 + k];
        }
    }

    // ---- grid barrier 1: all row-phase outputs visible ----
    grid_barrier(&g_bar1);

    // ---- epilogue: block b handles s = b*8 .. b*8+7, warp-per-s, k-parallel lanes ----
    {
        const unsigned char* lb = (const unsigned char*)is_leaf;
        const unsigned int*  lw = (const unsigned int*)is_leaf;
        const bool leaf = (lb[root] != 0) || (lw[root] == 0x3F800000u);

        const int s = b * 8 + warp;
        float lin;
        if (leaf) {
            lin = (lane == 0) ? g_P[8 * SS + s] : 0.0f;
        } else {
            const int k = lane & 3;          // lanes replicate over 4-lane groups
            const int i1 = sC1[s], i2 = sC2[s];
            const float inv = g_invcnt[s];
            const float q = expf(log_q[root * KK + k]);

            const float* PA = g_P + k * SS;
            const float* PB = g_P + (4 + k) * SS;
            float A  = PA[s],  B  = PB[s];
            float Af = PA[i1], Ag = PA[i2];
            float Bf = PB[i1], Bg = PB[i2];
            float sA = g_sums[k * SS + s];
            float sB = g_sums[(4 + k) * SS + s];

            float part = pS * (q * (Af * Bg + Ag * Bf))
                       + pD * (q * (A * B))
                       + (pT * inv) * (q * (A * sB + B * sA));
            // sum the 4 k-terms within the 4-lane group
            part += __shfl_xor_sync(0xffffffffu, part, 1);
            part += __shfl_xor_sync(0xffffffffu, part, 2);
            if (lane == 0) {
                float sl = g_P[8 * SS + i1] * g_En[i2] + g_P[8 * SS + i2] * g_En[i1];
                part += pS * sl;
            }
            lin = (lane == 0) ? part : 0.0f;
        }
        if (lane == 0) s_part[warp] = lin;
        __syncthreads();
        if (tid == 0) {
            float t = 0.0f;
            #pragma unroll
            for (int w2 = 0; w2 < 8; w2++) t += s_part[w2];
            g_ps[b] = t;
        }
    }

    // ---- grid barrier 2: partials visible ----
    grid_barrier(&g_bar2);

    // ---- block 0 final reduction: 128 partials, one log ----
    if (b == 0 && warp == 0) {
        float v = g_ps[lane] + g_ps[lane + 32] + g_ps[lane + 64] + g_ps[lane + 96];
        #pragma unroll
        for (int o = 16; o > 0; o >>= 1)
            v += __shfl_xor_sync(0xffffffffu, v, o);
        if (lane == 0) out[0] = logf(v);
    }
}

// ---------------- launch ----------------
extern "C" void kernel_launch(void* const* d_in, const int* in_sizes, int n_in,
                              void* d_out, int out_size)
{
    const float* log_delta  = (const float*)d_in[0];
    const float* log_tau    = (const float*)d_in[1];
    const float* log_lambda = (const float*)d_in[2];
    const float* E          = (const float*)d_in[3];
    const float* log_Pi     = (const float*)d_in[4];
    const int*   s_C1       = (const int*)  d_in[5];
    const int*   s_C2       = (const int*)  d_in[6];
    const float* recip      = (const float*)d_in[7];
    const int*   splits_c1  = (const int*)  d_in[8];
    const int*   splits_c2  = (const int*)  d_in[9];
    const float* log_q      = (const float*)d_in[10];
    const void*  is_leaf    = (const void*) d_in[11];
    const int*   root_id    = (const int*)  d_in[12];
    float* out = (float*)d_out;

    k_fused<<<NB, 256>>>(log_delta, log_tau, log_lambda, E, log_Pi,
                         s_C1, s_C2, recip, splits_c1, splits_c2,
                         log_q, is_leaf, root_id, out);
}